// round 13
// baseline (speedup 1.0000x reference)
#include <cuda_runtime.h>

#define D_DIM   768
#define F4_ROW  (D_DIM / 4)        // 192 float4 per row
#define F4_LANE 6                  // float4 per lane (192/32)
#define WARPS   8
#define NTHR    (WARPS * 32)       // 256 threads
#define RPW     8                  // rows per warp
#define LN_EPS  1e-6f

__global__ __launch_bounds__(NTHR)
void hier_attn_ln_kernel(const int*   __restrict__ ids,
                         const float* __restrict__ pooler,
                         const float* __restrict__ emb,     // (V,2)
                         const float* __restrict__ Wd,      // (2,D)
                         const float* __restrict__ bd,      // (D)
                         const float* __restrict__ gamma,   // (D)
                         const float* __restrict__ beta,    // (D)
                         float*       __restrict__ out,
                         int L)
{
    __shared__ float4 sG [F4_ROW];   // gamma
    __shared__ float4 sBE[F4_ROW];   // beta

    const int b    = blockIdx.y;
    const int warp = threadIdx.x >> 5;
    const int lane = threadIdx.x & 31;
    const int t    = threadIdx.x;

    // ---- stage gamma/beta into smem once per block ----
    {
        const float4* GG = reinterpret_cast<const float4*>(gamma);
        const float4* BE = reinterpret_cast<const float4*>(beta);
        if (t < F4_ROW) {
            sG [t] = GG[t];
            sBE[t] = BE[t];
        }
    }

    // ---- per-warp x vector in registers; Sx/xx reduced within the warp ----
    const int   id = __ldg(ids + b);
    const float e0 = __ldg(emb + 2 * id);
    const float e1 = __ldg(emb + 2 * id + 1);

    const float4* W0 = reinterpret_cast<const float4*>(Wd);
    const float4* W1 = reinterpret_cast<const float4*>(Wd + D_DIM);
    const float4* BB = reinterpret_cast<const float4*>(bd);

    float4 xv[F4_LANE];
    float Sx = 0.f, xx = 0.f;
    #pragma unroll
    for (int j = 0; j < F4_LANE; ++j) {
        const int c = lane + 32 * j;
        float4 w0 = W0[c], w1 = W1[c], bb = BB[c];
        float4 v;
        v.x = fmaf(e0, w0.x, fmaf(e1, w1.x, bb.x));
        v.y = fmaf(e0, w0.y, fmaf(e1, w1.y, bb.y));
        v.z = fmaf(e0, w0.z, fmaf(e1, w1.z, bb.z));
        v.w = fmaf(e0, w0.w, fmaf(e1, w1.w, bb.w));
        xv[j] = v;
        Sx += v.x + v.y + v.z + v.w;
        xx = fmaf(v.x, v.x, fmaf(v.y, v.y, fmaf(v.z, v.z, fmaf(v.w, v.w, xx))));
    }
    #pragma unroll
    for (int off = 16; off > 0; off >>= 1) {
        Sx += __shfl_xor_sync(0xffffffffu, Sx, off);
        xx += __shfl_xor_sync(0xffffffffu, xx, off);
    }

    __syncthreads();   // gamma/beta staged

    const int l0 = (blockIdx.x * WARPS + warp) * RPW;
    if (l0 >= L) return;
    const int nrows = min(RPW, L - l0);

    const float invD = 1.0f / (float)D_DIM;
    const float* rowPtr = pooler + ((size_t)b * L + l0) * D_DIM;
    float*       outPtr = out    + ((size_t)b * L + l0) * D_DIM;

    // ---- explicit double-buffered row pipeline ----
    float4 pbuf[2][F4_LANE];

    // loads: evict-first streaming (don't displace resident output lines in L2)
    #pragma unroll
    for (int j = 0; j < F4_LANE; ++j)
        pbuf[0][j] = __ldcs(reinterpret_cast<const float4*>(rowPtr) + lane + 32 * j);

    #pragma unroll
    for (int r = 0; r < RPW; ++r) {
        if (r >= nrows) break;
        float4 (&p)[F4_LANE]  = pbuf[r & 1];
        float4 (&pn)[F4_LANE] = pbuf[(r + 1) & 1];

        // prefetch next row BEFORE the dependent chain
        if (r + 1 < nrows) {
            const float4* nrow = reinterpret_cast<const float4*>(rowPtr + (size_t)(r + 1) * D_DIM);
            #pragma unroll
            for (int j = 0; j < F4_LANE; ++j)
                pn[j] = __ldcs(nrow + lane + 32 * j);
        }

        float pp = 0.f, px = 0.f, Sp = 0.f;
        #pragma unroll
        for (int j = 0; j < F4_LANE; ++j) {
            pp = fmaf(p[j].x, p[j].x,  fmaf(p[j].y, p[j].y,  fmaf(p[j].z, p[j].z,  fmaf(p[j].w, p[j].w,  pp))));
            px = fmaf(p[j].x, xv[j].x, fmaf(p[j].y, xv[j].y, fmaf(p[j].z, xv[j].z, fmaf(p[j].w, xv[j].w, px))));
            Sp += p[j].x + p[j].y + p[j].z + p[j].w;
        }
        #pragma unroll
        for (int off = 16; off > 0; off >>= 1) {
            pp += __shfl_xor_sync(0xffffffffu, pp, off);
            px += __shfl_xor_sync(0xffffffffu, px, off);
            Sp += __shfl_xor_sync(0xffffffffu, Sp, off);
        }

        // softmax weights via sigmoids: wp = sig(pp-px) + sig(px-xx); wx = 2 - wp
        float wp = __fdividef(1.f, 1.f + __expf(px - pp))
                 + __fdividef(1.f, 1.f + __expf(xx - px));
        float wx = 2.0f - wp;

        // analytic layernorm stats of summed = wp*p + wx*x
        float mean = (wp * Sp + wx * Sx) * invD;
        float ss2  = wp*wp*pp + 2.0f*wp*wx*px + wx*wx*xx;
        float inv  = rsqrtf(ss2 * invD - mean * mean + LN_EPS);
        float cwp  = wp * inv;
        float cwx  = wx * inv;
        float ncm  = -mean * inv;

        // stores: PLAIN write-back (evict-normal) — output stays resident in L2
        // across graph replays; it is rewritten before it ever drains to DRAM.
        float4* orow = reinterpret_cast<float4*>(outPtr + (size_t)r * D_DIM);
        #pragma unroll
        for (int j = 0; j < F4_LANE; ++j) {
            const int c = lane + 32 * j;
            const float4 g  = sG[c];
            const float4 be = sBE[c];
            float4 o;
            o.x = fmaf(fmaf(cwp, p[j].x, fmaf(cwx, xv[j].x, ncm)), g.x, be.x);
            o.y = fmaf(fmaf(cwp, p[j].y, fmaf(cwx, xv[j].y, ncm)), g.y, be.y);
            o.z = fmaf(fmaf(cwp, p[j].z, fmaf(cwx, xv[j].z, ncm)), g.z, be.z);
            o.w = fmaf(fmaf(cwp, p[j].w, fmaf(cwx, xv[j].w, ncm)), g.w, be.w);
            orow[c] = o;
        }
    }
}

extern "C" void kernel_launch(void* const* d_in, const int* in_sizes, int n_in,
                              void* d_out, int out_size)
{
    const int*   ids    = (const int*)  d_in[0];
    const float* pooler = (const float*)d_in[1];
    const float* emb    = (const float*)d_in[2];
    const float* Wd     = (const float*)d_in[3];
    const float* bd     = (const float*)d_in[4];
    const float* gamma  = (const float*)d_in[5];
    const float* beta   = (const float*)d_in[6];
    float* out = (float*)d_out;

    const int B = in_sizes[0];                      // ids is (B,1)
    const int L = in_sizes[1] / (B * D_DIM);        // pooler is (B,L,D)

    dim3 grid((L + WARPS * RPW - 1) / (WARPS * RPW), B);
    hier_attn_ln_kernel<<<grid, NTHR>>>(ids, pooler, emb, Wd, bd, gamma, beta, out, L);
}

// round 14
// speedup vs baseline: 1.2115x; 1.2115x over previous
#include <cuda_runtime.h>

#define D_DIM   768
#define F4_ROW  (D_DIM / 4)        // 192 float4 per row
#define F4_LANE 6                  // float4 per lane (192/32)
#define WARPS   8
#define NTHR    (WARPS * 32)       // 256 threads
#define RPW     8                  // rows per warp
#define LN_EPS  1e-6f

__global__ __launch_bounds__(NTHR, 2)   // pin 128 regs -> 2 CTA/SM
void hier_attn_ln_kernel(const int*   __restrict__ ids,
                         const float* __restrict__ pooler,
                         const float* __restrict__ emb,     // (V,2)
                         const float* __restrict__ Wd,      // (2,D)
                         const float* __restrict__ bd,      // (D)
                         const float* __restrict__ gamma,   // (D)
                         const float* __restrict__ beta,    // (D)
                         float*       __restrict__ out,
                         int L)
{
    __shared__ float4 sG [F4_ROW];   // gamma
    __shared__ float4 sBE[F4_ROW];   // beta

    const int b    = blockIdx.y;
    const int warp = threadIdx.x >> 5;
    const int lane = threadIdx.x & 31;
    const int t    = threadIdx.x;

    // ---- stage gamma/beta into smem once per block ----
    {
        const float4* GG = reinterpret_cast<const float4*>(gamma);
        const float4* BE = reinterpret_cast<const float4*>(beta);
        if (t < F4_ROW) {
            sG [t] = GG[t];
            sBE[t] = BE[t];
        }
    }

    // ---- per-warp x vector in registers; Sx/xx reduced within the warp ----
    const int   id = __ldg(ids + b);
    const float e0 = __ldg(emb + 2 * id);
    const float e1 = __ldg(emb + 2 * id + 1);

    const float4* W0 = reinterpret_cast<const float4*>(Wd);
    const float4* W1 = reinterpret_cast<const float4*>(Wd + D_DIM);
    const float4* BB = reinterpret_cast<const float4*>(bd);

    float4 xv[F4_LANE];
    float Sx = 0.f, xx = 0.f;
    #pragma unroll
    for (int j = 0; j < F4_LANE; ++j) {
        const int c = lane + 32 * j;
        float4 w0 = W0[c], w1 = W1[c], bb = BB[c];
        float4 v;
        v.x = fmaf(e0, w0.x, fmaf(e1, w1.x, bb.x));
        v.y = fmaf(e0, w0.y, fmaf(e1, w1.y, bb.y));
        v.z = fmaf(e0, w0.z, fmaf(e1, w1.z, bb.z));
        v.w = fmaf(e0, w0.w, fmaf(e1, w1.w, bb.w));
        xv[j] = v;
        Sx += v.x + v.y + v.z + v.w;
        xx = fmaf(v.x, v.x, fmaf(v.y, v.y, fmaf(v.z, v.z, fmaf(v.w, v.w, xx))));
    }
    #pragma unroll
    for (int off = 16; off > 0; off >>= 1) {
        Sx += __shfl_xor_sync(0xffffffffu, Sx, off);
        xx += __shfl_xor_sync(0xffffffffu, xx, off);
    }

    __syncthreads();   // gamma/beta staged

    const int l0 = (blockIdx.x * WARPS + warp) * RPW;
    if (l0 >= L) return;
    const int nrows = min(RPW, L - l0);

    const float invD = 1.0f / (float)D_DIM;
    const float* rowPtr = pooler + ((size_t)b * L + l0) * D_DIM;
    float*       outPtr = out    + ((size_t)b * L + l0) * D_DIM;

    // ---- explicit double-buffered row pipeline ----
    float4 pbuf[2][F4_LANE];

    // loads: evict-first streaming (don't displace resident output lines in L2)
    #pragma unroll
    for (int j = 0; j < F4_LANE; ++j)
        pbuf[0][j] = __ldcs(reinterpret_cast<const float4*>(rowPtr) + lane + 32 * j);

    #pragma unroll
    for (int r = 0; r < RPW; ++r) {
        if (r >= nrows) break;
        float4 (&p)[F4_LANE]  = pbuf[r & 1];
        float4 (&pn)[F4_LANE] = pbuf[(r + 1) & 1];

        // prefetch next row BEFORE the dependent chain
        if (r + 1 < nrows) {
            const float4* nrow = reinterpret_cast<const float4*>(rowPtr + (size_t)(r + 1) * D_DIM);
            #pragma unroll
            for (int j = 0; j < F4_LANE; ++j)
                pn[j] = __ldcs(nrow + lane + 32 * j);
        }

        float pp = 0.f, px = 0.f, Sp = 0.f;
        #pragma unroll
        for (int j = 0; j < F4_LANE; ++j) {
            pp = fmaf(p[j].x, p[j].x,  fmaf(p[j].y, p[j].y,  fmaf(p[j].z, p[j].z,  fmaf(p[j].w, p[j].w,  pp))));
            px = fmaf(p[j].x, xv[j].x, fmaf(p[j].y, xv[j].y, fmaf(p[j].z, xv[j].z, fmaf(p[j].w, xv[j].w, px))));
            Sp += p[j].x + p[j].y + p[j].z + p[j].w;
        }
        #pragma unroll
        for (int off = 16; off > 0; off >>= 1) {
            pp += __shfl_xor_sync(0xffffffffu, pp, off);
            px += __shfl_xor_sync(0xffffffffu, px, off);
            Sp += __shfl_xor_sync(0xffffffffu, Sp, off);
        }

        // 2x2 safe softmax; rows [pp,px] and [px,xx]  (R4-proven form)
        float m0  = fmaxf(pp, px);
        float e00 = __expf(pp - m0), e01 = __expf(px - m0);
        float a00 = e00 / (e00 + e01), a01 = 1.0f - a00;
        float m1  = fmaxf(px, xx);
        float e10 = __expf(px - m1), e11 = __expf(xx - m1);
        float a10 = e10 / (e10 + e11), a11 = 1.0f - a10;

        float wp = a00 + a10;
        float wx = a01 + a11;

        // analytic layernorm stats of summed = wp*p + wx*x
        float mean = (wp * Sp + wx * Sx) * invD;
        float ss2  = wp*wp*pp + 2.0f*wp*wx*px + wx*wx*xx;
        float var  = ss2 * invD - mean * mean;
        float inv  = rsqrtf(var + LN_EPS);
        float cwp  = wp * inv;
        float cwx  = wx * inv;
        float ncm  = -mean * inv;

        // stores: PLAIN write-back — output lines stay resident in L2 across
        // graph replays and are overwritten before draining to DRAM.
        float4* orow = reinterpret_cast<float4*>(outPtr + (size_t)r * D_DIM);
        #pragma unroll
        for (int j = 0; j < F4_LANE; ++j) {
            const int c = lane + 32 * j;
            const float4 g  = sG[c];
            const float4 be = sBE[c];
            float4 o;
            o.x = fmaf(fmaf(cwp, p[j].x, fmaf(cwx, xv[j].x, ncm)), g.x, be.x);
            o.y = fmaf(fmaf(cwp, p[j].y, fmaf(cwx, xv[j].y, ncm)), g.y, be.y);
            o.z = fmaf(fmaf(cwp, p[j].z, fmaf(cwx, xv[j].z, ncm)), g.z, be.z);
            o.w = fmaf(fmaf(cwp, p[j].w, fmaf(cwx, xv[j].w, ncm)), g.w, be.w);
            orow[c] = o;
        }
    }
}

extern "C" void kernel_launch(void* const* d_in, const int* in_sizes, int n_in,
                              void* d_out, int out_size)
{
    const int*   ids    = (const int*)  d_in[0];
    const float* pooler = (const float*)d_in[1];
    const float* emb    = (const float*)d_in[2];
    const float* Wd     = (const float*)d_in[3];
    const float* bd     = (const float*)d_in[4];
    const float* gamma  = (const float*)d_in[5];
    const float* beta   = (const float*)d_in[6];
    float* out = (float*)d_out;

    const int B = in_sizes[0];                      // ids is (B,1)
    const int L = in_sizes[1] / (B * D_DIM);        // pooler is (B,L,D)

    dim3 grid((L + WARPS * RPW - 1) / (WARPS * RPW), B);
    hier_attn_ln_kernel<<<grid, NTHR>>>(ids, pooler, emb, Wd, bd, gamma, beta, out, L);
}